// round 8
// baseline (speedup 1.0000x reference)
#include <cuda_runtime.h>
#include <cstdint>

constexpr int S = 2048, D = 64;
constexpr int BH = 32;
constexpr float SCALE = 0.125f;
constexpr size_t CTX_ELEMS = (size_t)BH * S * D;

constexpr int PQ = 68;    // sQ pitch (mult of 4 -> float4)
constexpr int PK = 134;   // sKt pitch (even -> 8B loads; 4-way store conflicts max)
constexpr int PV2 = 68;   // pass2 sV pitch (mult of 4)
constexpr int PP2 = 68;   // pass2 sP pitch (mult of 4)

__device__ float g_m[BH * S];
__device__ float g_l[BH * S];

// ---- packed fp32x2 helpers (FFMA2) ----
__device__ __forceinline__ unsigned long long pack2(float lo, float hi) {
    unsigned long long r;
    asm("mov.b64 %0, {%1, %2};" : "=l"(r) : "r"(__float_as_uint(lo)), "r"(__float_as_uint(hi)));
    return r;
}
__device__ __forceinline__ unsigned long long dup2(float x) { return pack2(x, x); }
__device__ __forceinline__ float2 unpack2(unsigned long long v) {
    unsigned int a, b;
    asm("mov.b64 {%0, %1}, %2;" : "=r"(a), "=r"(b) : "l"(v));
    return make_float2(__uint_as_float(a), __uint_as_float(b));
}
__device__ __forceinline__ void fma2(unsigned long long& d, unsigned long long a, unsigned long long b) {
    asm("fma.rn.f32x2 %0, %1, %2, %3;" : "=l"(d) : "l"(a), "l"(b), "l"(d));
}

// ---------------------------------------------------------------------------
// Pass 1: masked raw scores -> SC; online m/l -> g_m/g_l; zero-fill upper.
// Grid (8, 32): CTA pid does q-tiles {pid, 15-pid}. 256 threads, 8x8/thread.
// Double-buffered K tile, one __syncthreads per tile.
// ---------------------------------------------------------------------------
__global__ void __launch_bounds__(256, 2)
attn_pass1(const float* __restrict__ Q, const float* __restrict__ K,
           float* __restrict__ SC)
{
    extern __shared__ float sm[];
    float* sQ  = sm;                       // 128 x PQ
    float* sKt0 = sm + 128 * PQ;           // 64 x PK
    float* sKt1 = sKt0 + 64 * PK;          // 64 x PK

    const int tid = threadIdx.x;
    const int tx = tid & 15;
    const int ty = tid >> 4;
    const int pid = blockIdx.x;
    const int bh = blockIdx.y;

    // Zero-fill non-causal prob columns for both q-tiles
    {
        const float4 z = make_float4(0.f, 0.f, 0.f, 0.f);
#pragma unroll
        for (int half = 0; half < 2; ++half) {
            const int qt = half ? (15 - pid) : pid;
            const int c0 = (qt + 1) * 128;
            if (c0 < S) {
                const int w4 = (S - c0) >> 2;
                const int r0 = qt * 128;
                for (int i = tid; i < 128 * w4; i += 256) {
                    const int row = i / w4;
                    const int c4 = i - row * w4;
                    *((float4*)(SC + ((size_t)bh * S + r0 + row) * S + c0 + 4 * c4)) = z;
                }
            }
        }
    }

    for (int half = 0; half < 2; ++half) {
        const int qt = half ? (15 - pid) : pid;
        const int r0 = qt * 128;

        __syncthreads();
        {
            const float* qbase = Q + ((size_t)bh * S + r0) * D;
            for (int i = tid; i < 128 * 16; i += 256) {
                int row = i >> 4, c4 = i & 15;
                float4 v = ((const float4*)(qbase + row * D))[c4];
                *((float4*)(sQ + row * PQ + c4 * 4)) = v;
            }
            const float* kbase = K + ((size_t)bh * S) * D;
            for (int i = tid; i < 128 * 16; i += 256) {
                int col = i >> 4, c4 = i & 15;
                float4 v = ((const float4*)(kbase + col * D))[c4];
                sKt0[(4 * c4 + 0) * PK + col] = v.x;
                sKt0[(4 * c4 + 1) * PK + col] = v.y;
                sKt0[(4 * c4 + 2) * PK + col] = v.z;
                sKt0[(4 * c4 + 3) * PK + col] = v.w;
            }
        }

        float m[8], l[8];
#pragma unroll
        for (int rr = 0; rr < 8; rr++) { m[rr] = -1e30f; l[rr] = 0.0f; }

        for (int kt = 0; kt <= qt; ++kt) {
            __syncthreads();
            const float* sKt = (kt & 1) ? sKt1 : sKt0;

            unsigned long long acc[8][4];
#pragma unroll
            for (int rr = 0; rr < 8; rr++)
#pragma unroll
                for (int c = 0; c < 4; c++) acc[rr][c] = 0ull;

#pragma unroll 1
            for (int kk = 0; kk < 64; kk += 4) {
                float4 q4[8];
#pragma unroll
                for (int rr = 0; rr < 8; rr++)
                    q4[rr] = *((const float4*)(sQ + (ty + 16 * rr) * PQ + kk));
#pragma unroll
                for (int s = 0; s < 4; s++) {
                    unsigned long long kp[4];
#pragma unroll
                    for (int c = 0; c < 4; c++)
                        kp[c] = *((const unsigned long long*)(sKt + (kk + s) * PK + 2 * tx + 32 * c));
#pragma unroll
                    for (int rr = 0; rr < 8; rr++) {
                        const float qs = (s == 0) ? q4[rr].x : (s == 1) ? q4[rr].y
                                       : (s == 2) ? q4[rr].z : q4[rr].w;
                        unsigned long long qd = dup2(qs);
#pragma unroll
                        for (int c = 0; c < 4; c++) fma2(acc[rr][c], qd, kp[c]);
                    }
                }
            }

            const bool diag = (kt == qt);
#pragma unroll
            for (int rr = 0; rr < 8; rr++) {
                const int row = ty + 16 * rr;
                float sv[8];
                float tmax = -1e30f;
#pragma unroll
                for (int c = 0; c < 4; c++) {
                    float2 p = unpack2(acc[rr][c]);
                    const int col = 2 * tx + 32 * c;
                    float s0 = p.x * SCALE;
                    float s1 = p.y * SCALE;
                    if (diag) {
                        if (col > row) s0 = -1e9f;
                        if (col + 1 > row) s1 = -1e9f;
                    }
                    sv[2 * c] = s0;
                    sv[2 * c + 1] = s1;
                    tmax = fmaxf(tmax, fmaxf(s0, s1));
                }
                tmax = fmaxf(tmax, __shfl_xor_sync(0xffffffffu, tmax, 1));
                tmax = fmaxf(tmax, __shfl_xor_sync(0xffffffffu, tmax, 2));
                tmax = fmaxf(tmax, __shfl_xor_sync(0xffffffffu, tmax, 4));
                tmax = fmaxf(tmax, __shfl_xor_sync(0xffffffffu, tmax, 8));

                const float mn = fmaxf(m[rr], tmax);
                float psum = 0.0f;
#pragma unroll
                for (int cc = 0; cc < 8; cc++) psum += __expf(sv[cc] - mn);
                psum += __shfl_xor_sync(0xffffffffu, psum, 1);
                psum += __shfl_xor_sync(0xffffffffu, psum, 2);
                psum += __shfl_xor_sync(0xffffffffu, psum, 4);
                psum += __shfl_xor_sync(0xffffffffu, psum, 8);

                l[rr] = l[rr] * __expf(m[rr] - mn) + psum;
                m[rr] = mn;

                float* dst = SC + ((size_t)bh * S + r0 + row) * S + kt * 128;
#pragma unroll
                for (int c = 0; c < 4; c++)
                    *((float2*)(dst + 2 * tx + 32 * c)) = make_float2(sv[2 * c], sv[2 * c + 1]);
            }

            if (kt < qt) {
                float* sKn = ((kt + 1) & 1) ? sKt1 : sKt0;
                const float* kbase = K + ((size_t)bh * S + (kt + 1) * 128) * D;
                for (int i = tid; i < 128 * 16; i += 256) {
                    int col = i >> 4, c4 = i & 15;
                    float4 v = ((const float4*)(kbase + col * D))[c4];
                    sKn[(4 * c4 + 0) * PK + col] = v.x;
                    sKn[(4 * c4 + 1) * PK + col] = v.y;
                    sKn[(4 * c4 + 2) * PK + col] = v.z;
                    sKn[(4 * c4 + 3) * PK + col] = v.w;
                }
            }
        }

        if (tx == 0) {
#pragma unroll
            for (int rr = 0; rr < 8; rr++) {
                const int gi = bh * S + r0 + ty + 16 * rr;
                g_m[gi] = m[rr];
                g_l[gi] = l[rr];
            }
        }
    }
}

// ---------------------------------------------------------------------------
// Pass 2: probs = exp(s-m)/l -> gmem + smem; context = P @ V.
// Grid (16, 32): one 128-row q-tile per CTA; 64-wide k-tiles (2*(qt+1) of them).
// 256 threads, smem 52KB -> 3 CTAs/SM. Prob phase: 8 rows x 4 cols (float4).
// PV: 4 rows x 8 d per thread, float4 LDS.
// ---------------------------------------------------------------------------
__global__ void __launch_bounds__(256, 3)
attn_pass2(const float* __restrict__ V, float* __restrict__ SC,
           float* __restrict__ CTX)
{
    extern __shared__ float sm[];
    float* sV = sm;                 // 64 x PV2
    float* sP = sm + 64 * PV2;      // 128 x PP2

    const int tid = threadIdx.x;
    // prob phase: 16 col-lanes (4 cols each) x 16 row-groups (8 rows each)
    const int tx = tid & 15;
    const int ty = tid >> 4;
    // PV phase: 8 d-lanes (8 d each) x 32 row-groups (4 rows each)
    const int dgrp = tid & 7;
    const int rowgrp = tid >> 3;
    const int qt = blockIdx.x;
    const int bh = blockIdx.y;
    const int r0 = qt * 128;

    float m[8], rl[8];
#pragma unroll
    for (int rr = 0; rr < 8; rr++) {
        const int gi = bh * S + r0 + ty * 8 + rr;
        m[rr] = g_m[gi];
        rl[rr] = 1.0f / g_l[gi];
    }

    unsigned long long acc[4][4];
#pragma unroll
    for (int rr = 0; rr < 4; rr++)
#pragma unroll
        for (int dp = 0; dp < 4; dp++) acc[rr][dp] = 0ull;

    const int ntiles = 2 * (qt + 1);
    for (int kt = 0; kt < ntiles; ++kt) {
        __syncthreads();   // prior PV done before overwriting sV / sP
        {
            const float* vbase = V + ((size_t)bh * S + kt * 64) * D;
            for (int i = tid; i < 64 * 16; i += 256) {
                int row = i >> 4, c4 = i & 15;
                float4 v = ((const float4*)(vbase + row * D))[c4];
                *((float4*)(sV + row * PV2 + 4 * c4)) = v;
            }
        }

        // probs: float4 read scores, exp, float4 write gmem + smem
#pragma unroll 1
        for (int rr = 0; rr < 8; rr++) {
            const int row = ty * 8 + rr;
            float* srow = SC + ((size_t)bh * S + r0 + row) * S + kt * 64;
            const int col = 4 * tx;
            float4 s4 = *((const float4*)(srow + col));
            float4 p4;
            p4.x = __expf(s4.x - m[rr]) * rl[rr];
            p4.y = __expf(s4.y - m[rr]) * rl[rr];
            p4.z = __expf(s4.z - m[rr]) * rl[rr];
            p4.w = __expf(s4.w - m[rr]) * rl[rr];
            *((float4*)(srow + col)) = p4;
            *((float4*)(sP + row * PP2 + col)) = p4;
        }
        __syncthreads();

        // PV: ctx[row][d] += p[row][c] * v[c][d]
#pragma unroll 1
        for (int c = 0; c < 64; c += 4) {
            float4 p4[4];
#pragma unroll
            for (int rr = 0; rr < 4; rr++)
                p4[rr] = *((const float4*)(sP + (rowgrp * 4 + rr) * PP2 + c));
#pragma unroll
            for (int s = 0; s < 4; s++) {
                const float* vrow = sV + (c + s) * PV2 + dgrp * 8;
                unsigned long long vv[4];
                {
                    ulonglong2 a = *((const ulonglong2*)(vrow));
                    ulonglong2 b = *((const ulonglong2*)(vrow + 4));
                    vv[0] = a.x; vv[1] = a.y; vv[2] = b.x; vv[3] = b.y;
                }
#pragma unroll
                for (int rr = 0; rr < 4; rr++) {
                    const float ps = (s == 0) ? p4[rr].x : (s == 1) ? p4[rr].y
                                   : (s == 2) ? p4[rr].z : p4[rr].w;
                    unsigned long long pd = dup2(ps);
#pragma unroll
                    for (int dp = 0; dp < 4; dp++) fma2(acc[rr][dp], pd, vv[dp]);
                }
            }
        }
    }

    // Write context: rows rowgrp*4+rr, d = dgrp*8 .. +7 (two float4)
#pragma unroll
    for (int rr = 0; rr < 4; rr++) {
        const int row = rowgrp * 4 + rr;
        float* crow = CTX + ((size_t)bh * S + r0 + row) * D + dgrp * 8;
        float2 a = unpack2(acc[rr][0]);
        float2 b = unpack2(acc[rr][1]);
        float2 c2 = unpack2(acc[rr][2]);
        float2 d2 = unpack2(acc[rr][3]);
        *((float4*)(crow))     = make_float4(a.x, a.y, b.x, b.y);
        *((float4*)(crow + 4)) = make_float4(c2.x, c2.y, d2.x, d2.y);
    }
}

// ---------------------------------------------------------------------------
extern "C" void kernel_launch(void* const* d_in, const int* in_sizes, int n_in,
                              void* d_out, int out_size)
{
    const float* q = (const float*)d_in[0];
    const float* k = (const float*)d_in[1];
    const float* v = (const float*)d_in[2];

    float* out = (float*)d_out;
    float* ctx = out;                 // [BH, S, D]
    float* sc  = out + CTX_ELEMS;     // [BH, S, S]

    const int smem1 = (128 * PQ + 2 * 64 * PK) * sizeof(float);  // 103,424 B
    const int smem2 = (64 * PV2 + 128 * PP2) * sizeof(float);    // 52,224 B
    cudaFuncSetAttribute(attn_pass1, cudaFuncAttributeMaxDynamicSharedMemorySize, smem1);
    cudaFuncSetAttribute(attn_pass2, cudaFuncAttributeMaxDynamicSharedMemorySize, smem2);

    attn_pass1<<<dim3(8, BH), 256, smem1>>>(q, k, sc);
    attn_pass2<<<dim3(16, BH), 256, smem2>>>(v, sc, ctx);
}

// round 10
// speedup vs baseline: 1.1897x; 1.1897x over previous
#include <cuda_runtime.h>
#include <cstdint>

constexpr int S = 2048, D = 64;
constexpr int BH = 32;
constexpr float SCALE = 0.125f;
constexpr size_t CTX_ELEMS = (size_t)BH * S * D;

constexpr int PQ = 68;    // sQ pitch (mult of 4 -> float4)
constexpr int PK = 134;   // sKt pitch (even -> 8B loads)
constexpr int PV = 68;    // pass2 sV pitch (mult of 4 -> 16B rows)
constexpr int PP = 132;   // pass2 sP pitch (mult of 4 -> 16B rows)

__device__ float g_m[BH * S];
__device__ float g_l[BH * S];

// ---- packed fp32x2 helpers (FFMA2) ----
__device__ __forceinline__ unsigned long long pack2(float lo, float hi) {
    unsigned long long r;
    asm("mov.b64 %0, {%1, %2};" : "=l"(r) : "r"(__float_as_uint(lo)), "r"(__float_as_uint(hi)));
    return r;
}
__device__ __forceinline__ unsigned long long dup2(float x) { return pack2(x, x); }
__device__ __forceinline__ float2 unpack2(unsigned long long v) {
    unsigned int a, b;
    asm("mov.b64 {%0, %1}, %2;" : "=r"(a), "=r"(b) : "l"(v));
    return make_float2(__uint_as_float(a), __uint_as_float(b));
}
__device__ __forceinline__ void fma2(unsigned long long& d, unsigned long long a, unsigned long long b) {
    asm("fma.rn.f32x2 %0, %1, %2, %3;" : "=l"(d) : "l"(a), "l"(b), "l"(d));
}

// ---------------------------------------------------------------------------
// Pass 1: masked raw scores -> SC; online m/l -> g_m/g_l; zero-fill upper.
// Grid (8, 32): CTA pid does q-tiles {pid, 15-pid}. 256 threads, 8x8/thread.
// ---------------------------------------------------------------------------
__global__ void __launch_bounds__(256, 2)
attn_pass1(const float* __restrict__ Q, const float* __restrict__ K,
           float* __restrict__ SC)
{
    extern __shared__ float sm[];
    float* sQ  = sm;                       // 128 x PQ
    float* sKt0 = sm + 128 * PQ;           // 64 x PK
    float* sKt1 = sKt0 + 64 * PK;          // 64 x PK

    const int tid = threadIdx.x;
    const int tx = tid & 15;
    const int ty = tid >> 4;
    const int pid = blockIdx.x;
    const int bh = blockIdx.y;

    // Zero-fill non-causal prob columns for both q-tiles
    {
        const float4 z = make_float4(0.f, 0.f, 0.f, 0.f);
#pragma unroll
        for (int half = 0; half < 2; ++half) {
            const int qt = half ? (15 - pid) : pid;
            const int c0 = (qt + 1) * 128;
            if (c0 < S) {
                const int w4 = (S - c0) >> 2;
                const int r0 = qt * 128;
                for (int i = tid; i < 128 * w4; i += 256) {
                    const int row = i / w4;
                    const int c4 = i - row * w4;
                    *((float4*)(SC + ((size_t)bh * S + r0 + row) * S + c0 + 4 * c4)) = z;
                }
            }
        }
    }

    for (int half = 0; half < 2; ++half) {
        const int qt = half ? (15 - pid) : pid;
        const int r0 = qt * 128;

        __syncthreads();
        {
            const float* qbase = Q + ((size_t)bh * S + r0) * D;
            for (int i = tid; i < 128 * 16; i += 256) {
                int row = i >> 4, c4 = i & 15;
                float4 v = ((const float4*)(qbase + row * D))[c4];
                *((float4*)(sQ + row * PQ + c4 * 4)) = v;
            }
            const float* kbase = K + ((size_t)bh * S) * D;
            for (int i = tid; i < 128 * 16; i += 256) {
                int col = i >> 4, c4 = i & 15;
                float4 v = ((const float4*)(kbase + col * D))[c4];
                sKt0[(4 * c4 + 0) * PK + col] = v.x;
                sKt0[(4 * c4 + 1) * PK + col] = v.y;
                sKt0[(4 * c4 + 2) * PK + col] = v.z;
                sKt0[(4 * c4 + 3) * PK + col] = v.w;
            }
        }

        float m[8], l[8];
#pragma unroll
        for (int rr = 0; rr < 8; rr++) { m[rr] = -1e30f; l[rr] = 0.0f; }

        for (int kt = 0; kt <= qt; ++kt) {
            __syncthreads();
            const float* sKt = (kt & 1) ? sKt1 : sKt0;

            unsigned long long acc[8][4];
#pragma unroll
            for (int rr = 0; rr < 8; rr++)
#pragma unroll
                for (int c = 0; c < 4; c++) acc[rr][c] = 0ull;

#pragma unroll 1
            for (int kk = 0; kk < 64; kk += 4) {
                float4 q4[8];
#pragma unroll
                for (int rr = 0; rr < 8; rr++)
                    q4[rr] = *((const float4*)(sQ + (ty + 16 * rr) * PQ + kk));
#pragma unroll
                for (int s = 0; s < 4; s++) {
                    unsigned long long kp[4];
#pragma unroll
                    for (int c = 0; c < 4; c++)
                        kp[c] = *((const unsigned long long*)(sKt + (kk + s) * PK + 2 * tx + 32 * c));
#pragma unroll
                    for (int rr = 0; rr < 8; rr++) {
                        const float qs = (s == 0) ? q4[rr].x : (s == 1) ? q4[rr].y
                                       : (s == 2) ? q4[rr].z : q4[rr].w;
                        unsigned long long qd = dup2(qs);
#pragma unroll
                        for (int c = 0; c < 4; c++) fma2(acc[rr][c], qd, kp[c]);
                    }
                }
            }

            const bool diag = (kt == qt);
#pragma unroll
            for (int rr = 0; rr < 8; rr++) {
                const int row = ty + 16 * rr;
                float sv[8];
                float tmax = -1e30f;
#pragma unroll
                for (int c = 0; c < 4; c++) {
                    float2 p = unpack2(acc[rr][c]);
                    const int col = 2 * tx + 32 * c;
                    float s0 = p.x * SCALE;
                    float s1 = p.y * SCALE;
                    if (diag) {
                        if (col > row) s0 = -1e9f;
                        if (col + 1 > row) s1 = -1e9f;
                    }
                    sv[2 * c] = s0;
                    sv[2 * c + 1] = s1;
                    tmax = fmaxf(tmax, fmaxf(s0, s1));
                }
                tmax = fmaxf(tmax, __shfl_xor_sync(0xffffffffu, tmax, 1));
                tmax = fmaxf(tmax, __shfl_xor_sync(0xffffffffu, tmax, 2));
                tmax = fmaxf(tmax, __shfl_xor_sync(0xffffffffu, tmax, 4));
                tmax = fmaxf(tmax, __shfl_xor_sync(0xffffffffu, tmax, 8));

                const float mn = fmaxf(m[rr], tmax);
                float psum = 0.0f;
#pragma unroll
                for (int cc = 0; cc < 8; cc++) psum += __expf(sv[cc] - mn);
                psum += __shfl_xor_sync(0xffffffffu, psum, 1);
                psum += __shfl_xor_sync(0xffffffffu, psum, 2);
                psum += __shfl_xor_sync(0xffffffffu, psum, 4);
                psum += __shfl_xor_sync(0xffffffffu, psum, 8);

                l[rr] = l[rr] * __expf(m[rr] - mn) + psum;
                m[rr] = mn;

                float* dst = SC + ((size_t)bh * S + r0 + row) * S + kt * 128;
#pragma unroll
                for (int c = 0; c < 4; c++)
                    *((float2*)(dst + 2 * tx + 32 * c)) = make_float2(sv[2 * c], sv[2 * c + 1]);
            }

            if (kt < qt) {
                float* sKn = ((kt + 1) & 1) ? sKt1 : sKt0;
                const float* kbase = K + ((size_t)bh * S + (kt + 1) * 128) * D;
                for (int i = tid; i < 128 * 16; i += 256) {
                    int col = i >> 4, c4 = i & 15;
                    float4 v = ((const float4*)(kbase + col * D))[c4];
                    sKn[(4 * c4 + 0) * PK + col] = v.x;
                    sKn[(4 * c4 + 1) * PK + col] = v.y;
                    sKn[(4 * c4 + 2) * PK + col] = v.z;
                    sKn[(4 * c4 + 3) * PK + col] = v.w;
                }
            }
        }

        if (tx == 0) {
#pragma unroll
            for (int rr = 0; rr < 8; rr++) {
                const int gi = bh * S + r0 + ty + 16 * rr;
                g_m[gi] = m[rr];
                g_l[gi] = l[rr];
            }
        }
    }
}

// ---------------------------------------------------------------------------
// Pass 2: probs = exp(s-m)/l -> gmem + smem; context = P @ V.
// Grid (8, 32) paired q-tiles, TK=128, 256 threads, 2 CTAs/SM.
// Prob phase: 8 rows x 8 cols per thread, float4 IO.
// PV phase: 4 rows x 8 d per thread, float4/LDS.128 inner loop (c-step 4).
// ---------------------------------------------------------------------------
__global__ void __launch_bounds__(256, 2)
attn_pass2(const float* __restrict__ V, float* __restrict__ SC,
           float* __restrict__ CTX)
{
    extern __shared__ float sm[];
    float* sV = sm;               // 128 x PV
    float* sP = sm + 128 * PV;    // 128 x PP

    const int tid = threadIdx.x;
    // prob phase: 16 col-lanes (4 cols x 2 chunks) x 16 row-groups (8 rows each)
    const int tx = tid & 15;
    const int ty = tid >> 4;
    // PV phase: 8 d-lanes (8 d each) x 32 row-groups (4 rows each)
    const int dgrp = tid & 7;
    const int rowgrp = tid >> 3;
    const int pid = blockIdx.x;
    const int bh = blockIdx.y;

    for (int half = 0; half < 2; ++half) {
        const int qt = half ? (15 - pid) : pid;
        const int r0 = qt * 128;

        float m[8], rl[8];
#pragma unroll
        for (int rr = 0; rr < 8; rr++) {
            const int gi = bh * S + r0 + ty * 8 + rr;
            m[rr] = g_m[gi];
            rl[rr] = 1.0f / g_l[gi];
        }

        unsigned long long acc[4][4];
#pragma unroll
        for (int rr = 0; rr < 4; rr++)
#pragma unroll
            for (int dp = 0; dp < 4; dp++) acc[rr][dp] = 0ull;

        for (int kt = 0; kt <= qt; ++kt) {
            __syncthreads();  // prior PV done before overwriting sV / sP
            {
                const float* vbase = V + ((size_t)bh * S + kt * 128) * D;
                for (int i = tid; i < 128 * 16; i += 256) {
                    int row = i >> 4, c4 = i & 15;
                    float4 v = ((const float4*)(vbase + row * D))[c4];
                    *((float4*)(sV + row * PV + 4 * c4)) = v;
                }
            }

            // probs: float4 read scores, exp, float4 write gmem + smem
#pragma unroll 1
            for (int rr = 0; rr < 8; rr++) {
                const int row = ty * 8 + rr;
                float* srow = SC + ((size_t)bh * S + r0 + row) * S + kt * 128;
#pragma unroll
                for (int cc = 0; cc < 2; cc++) {
                    const int col = 4 * tx + 64 * cc;
                    float4 s4 = *((const float4*)(srow + col));
                    float4 p4;
                    p4.x = __expf(s4.x - m[rr]) * rl[rr];
                    p4.y = __expf(s4.y - m[rr]) * rl[rr];
                    p4.z = __expf(s4.z - m[rr]) * rl[rr];
                    p4.w = __expf(s4.w - m[rr]) * rl[rr];
                    *((float4*)(srow + col)) = p4;
                    *((float4*)(sP + row * PP + col)) = p4;
                }
            }
            __syncthreads();

            // PV: ctx[row][d] += p[row][c] * v[c][d], float4 granularity
#pragma unroll 1
            for (int c = 0; c < 128; c += 4) {
                float4 p4[4];
#pragma unroll
                for (int rr = 0; rr < 4; rr++)
                    p4[rr] = *((const float4*)(sP + (rowgrp * 4 + rr) * PP + c));
#pragma unroll
                for (int s = 0; s < 4; s++) {
                    const float* vrow = sV + (c + s) * PV + dgrp * 8;
                    unsigned long long vv[4];
                    {
                        ulonglong2 a = *((const ulonglong2*)(vrow));
                        ulonglong2 b = *((const ulonglong2*)(vrow + 4));
                        vv[0] = a.x; vv[1] = a.y; vv[2] = b.x; vv[3] = b.y;
                    }
#pragma unroll
                    for (int rr = 0; rr < 4; rr++) {
                        const float ps = (s == 0) ? p4[rr].x : (s == 1) ? p4[rr].y
                                       : (s == 2) ? p4[rr].z : p4[rr].w;
                        unsigned long long pd = dup2(ps);
#pragma unroll
                        for (int dp = 0; dp < 4; dp++) fma2(acc[rr][dp], pd, vv[dp]);
                    }
                }
            }
        }

        // Write context: rows rowgrp*4+rr, d = dgrp*8 .. +7 (two float4)
#pragma unroll
        for (int rr = 0; rr < 4; rr++) {
            const int row = rowgrp * 4 + rr;
            float* crow = CTX + ((size_t)bh * S + r0 + row) * D + dgrp * 8;
            float2 a = unpack2(acc[rr][0]);
            float2 b = unpack2(acc[rr][1]);
            float2 c2 = unpack2(acc[rr][2]);
            float2 d2 = unpack2(acc[rr][3]);
            *((float4*)(crow))     = make_float4(a.x, a.y, b.x, b.y);
            *((float4*)(crow + 4)) = make_float4(c2.x, c2.y, d2.x, d2.y);
        }

        // reset accumulators for second half
#pragma unroll
        for (int rr = 0; rr < 4; rr++)
#pragma unroll
            for (int dp = 0; dp < 4; dp++) acc[rr][dp] = 0ull;
    }
}

// ---------------------------------------------------------------------------
extern "C" void kernel_launch(void* const* d_in, const int* in_sizes, int n_in,
                              void* d_out, int out_size)
{
    const float* q = (const float*)d_in[0];
    const float* k = (const float*)d_in[1];
    const float* v = (const float*)d_in[2];

    float* out = (float*)d_out;
    float* ctx = out;                 // [BH, S, D]
    float* sc  = out + CTX_ELEMS;     // [BH, S, S]

    const int smem1 = (128 * PQ + 2 * 64 * PK) * sizeof(float);  // 103,424 B
    const int smem2 = (128 * PV + 128 * PP) * sizeof(float);     // 102,400 B
    cudaFuncSetAttribute(attn_pass1, cudaFuncAttributeMaxDynamicSharedMemorySize, smem1);
    cudaFuncSetAttribute(attn_pass2, cudaFuncAttributeMaxDynamicSharedMemorySize, smem2);

    attn_pass1<<<dim3(8, BH), 256, smem1>>>(q, k, sc);
    attn_pass2<<<dim3(8, BH), 256, smem2>>>(v, sc, ctx);
}

// round 14
// speedup vs baseline: 1.3138x; 1.1043x over previous
#include <cuda_runtime.h>
#include <cuda_bf16.h>
#include <cstdint>

constexpr int S = 2048, D = 64;
constexpr int BH = 32;
constexpr float SCALE = 0.125f;
constexpr size_t CTX_ELEMS = (size_t)BH * S * D;

// pass2 smem pitches (unchanged best)
constexpr int PV = 68;
constexpr int PP = 132;

__device__ float g_m[BH * S];
__device__ float g_l[BH * S];

// ---- packed fp32x2 helpers (pass2) ----
__device__ __forceinline__ unsigned long long pack2(float lo, float hi) {
    unsigned long long r;
    asm("mov.b64 %0, {%1, %2};" : "=l"(r) : "r"(__float_as_uint(lo)), "r"(__float_as_uint(hi)));
    return r;
}
__device__ __forceinline__ unsigned long long dup2(float x) { return pack2(x, x); }
__device__ __forceinline__ float2 unpack2(unsigned long long v) {
    unsigned int a, b;
    asm("mov.b64 {%0, %1}, %2;" : "=r"(a), "=r"(b) : "l"(v));
    return make_float2(__uint_as_float(a), __uint_as_float(b));
}
__device__ __forceinline__ void fma2(unsigned long long& d, unsigned long long a, unsigned long long b) {
    asm("fma.rn.f32x2 %0, %1, %2, %3;" : "=l"(d) : "l"(a), "l"(b), "l"(d));
}

// ---- bf16 split helpers ----
__device__ __forceinline__ uint32_t bf2pack(float a, float b) {
    __nv_bfloat162 t = __floats2bfloat162_rn(a, b);
    return *reinterpret_cast<uint32_t*>(&t);
}
__device__ __forceinline__ float bfres(float a) {
    return a - __bfloat162float(__float2bfloat16(a));
}

// ---- smem addressing ----
__device__ __forceinline__ uint32_t smem_u32(const void* p) {
    uint32_t a;
    asm("{ .reg .u64 t; cvta.to.shared.u64 t, %1; cvt.u32.u64 %0, t; }" : "=r"(a) : "l"(p));
    return a;
}
__device__ __forceinline__ uint32_t sw128(uint32_t off) { return off ^ ((off >> 3) & 0x70); }

// ---- ldmatrix / mma wrappers (plain sm_80+ PTX, legal on compute_103) ----
__device__ __forceinline__ void ldsm_x4(uint32_t* r, uint32_t addr) {
    asm volatile("ldmatrix.sync.aligned.m8n8.x4.shared.b16 {%0,%1,%2,%3}, [%4];"
                 : "=r"(r[0]), "=r"(r[1]), "=r"(r[2]), "=r"(r[3]) : "r"(addr));
}
// B from [n][k] (k-contiguous) tile: NON-trans gives lane -> {B[2*tid][gid], B[2*tid+1][gid]}
__device__ __forceinline__ void ldsm_x2(uint32_t* r, uint32_t addr) {
    asm volatile("ldmatrix.sync.aligned.m8n8.x2.shared.b16 {%0,%1}, [%2];"
                 : "=r"(r[0]), "=r"(r[1]) : "r"(addr));
}
__device__ __forceinline__ void mma_bf16(float* d, const uint32_t* a, const uint32_t* b) {
    asm volatile(
        "mma.sync.aligned.m16n8k16.row.col.f32.bf16.bf16.f32 "
        "{%0,%1,%2,%3}, {%4,%5,%6,%7}, {%8,%9}, {%0,%1,%2,%3};"
        : "+f"(d[0]), "+f"(d[1]), "+f"(d[2]), "+f"(d[3])
        : "r"(a[0]), "r"(a[1]), "r"(a[2]), "r"(a[3]), "r"(b[0]), "r"(b[1]));
}

// pass1 smem layout (bytes): 4 tiles of 128 rows x 64 bf16 (128B rows, SW128)
constexpr int TILE_B = 128 * 128;    // 16384
constexpr int SM_QHI = 0;
constexpr int SM_QLO = TILE_B;
constexpr int SM_KHI = 2 * TILE_B;
constexpr int SM_KLO = 3 * TILE_B;
constexpr int SM1_TOTAL = 4 * TILE_B;   // 65536 B

// ---------------------------------------------------------------------------
// Pass 1 (HMMA): scores = (Q K^T)*scale masked -> SC; m/l; zero-fill upper.
// Grid (8,32) paired q-tiles. 128 threads = 4 warps; warp w owns rows
// w*32..w*32+31 (2 m16 blocks x 16 n8 tiles). bf16x3: QhKh + QhKl + QlKh.
// ---------------------------------------------------------------------------
__global__ void __launch_bounds__(128, 2)
attn_pass1(const float* __restrict__ Q, const float* __restrict__ K,
           float* __restrict__ SC)
{
    extern __shared__ char smem[];
    const uint32_t sb = smem_u32(smem);

    const int tid = threadIdx.x;
    const int lane = tid & 31;
    const int warp = tid >> 5;
    const int pid = blockIdx.x;
    const int bh = blockIdx.y;

    // Zero-fill non-causal prob columns for both q-tiles
    {
        const float4 z = make_float4(0.f, 0.f, 0.f, 0.f);
#pragma unroll
        for (int half = 0; half < 2; ++half) {
            const int qt = half ? (15 - pid) : pid;
            const int c0 = (qt + 1) * 128;
            if (c0 < S) {
                const int w4 = (S - c0) >> 2;
                const int r0 = qt * 128;
                for (int i = tid; i < 128 * w4; i += 128) {
                    const int row = i / w4;
                    const int c4 = i - row * w4;
                    *((float4*)(SC + ((size_t)bh * S + r0 + row) * S + c0 + 4 * c4)) = z;
                }
            }
        }
    }

    for (int half = 0; half < 2; ++half) {
        const int qt = half ? (15 - pid) : pid;
        const int r0 = qt * 128;

        __syncthreads();   // previous half done with all tiles
        // Load + split Q (128x64 f32 -> bf16 hi/lo, SW128 128B rows)
        {
            const float* qbase = Q + ((size_t)bh * S + r0) * D;
            for (int i = tid; i < 128 * 16; i += 128) {
                int row = i >> 4, c4 = i & 15;
                float4 v = ((const float4*)(qbase + row * D))[c4];
                uint32_t off = sw128((uint32_t)(row * 128 + c4 * 8));
                *((uint2*)(smem + SM_QHI + off)) =
                    make_uint2(bf2pack(v.x, v.y), bf2pack(v.z, v.w));
                *((uint2*)(smem + SM_QLO + off)) =
                    make_uint2(bf2pack(bfres(v.x), bfres(v.y)), bf2pack(bfres(v.z), bfres(v.w)));
            }
        }

        // per-thread softmax state for its 4 owned rows [mb][rg]
        float m[2][2], l[2][2];
#pragma unroll
        for (int a = 0; a < 2; a++)
#pragma unroll
            for (int b = 0; b < 2; b++) { m[a][b] = -1e30f; l[a][b] = 0.0f; }

        for (int kt = 0; kt <= qt; ++kt) {
            __syncthreads();   // prior epilogue done; K tiles free
            {
                const float* kbase = K + ((size_t)bh * S + kt * 128) * D;
                for (int i = tid; i < 128 * 16; i += 128) {
                    int row = i >> 4, c4 = i & 15;
                    float4 v = ((const float4*)(kbase + row * D))[c4];
                    uint32_t off = sw128((uint32_t)(row * 128 + c4 * 8));
                    *((uint2*)(smem + SM_KHI + off)) =
                        make_uint2(bf2pack(v.x, v.y), bf2pack(v.z, v.w));
                    *((uint2*)(smem + SM_KLO + off)) =
                        make_uint2(bf2pack(bfres(v.x), bfres(v.y)),
                                   bf2pack(bfres(v.z), bfres(v.w)));
                }
            }
            __syncthreads();   // tiles ready

            float acc[2][16][4];
#pragma unroll
            for (int mb = 0; mb < 2; mb++)
#pragma unroll
                for (int j = 0; j < 16; j++)
#pragma unroll
                    for (int x = 0; x < 4; x++) acc[mb][j][x] = 0.0f;

#pragma unroll
            for (int p = 0; p < 3; ++p) {
                const uint32_t abase = sb + ((p == 2) ? SM_QLO : SM_QHI);
                const uint32_t bbase = sb + ((p == 1) ? SM_KLO : SM_KHI);
#pragma unroll
                for (int ks = 0; ks < 4; ++ks) {
                    const int kk = 16 * ks;
                    uint32_t afrag[2][4];
#pragma unroll
                    for (int mb = 0; mb < 2; mb++) {
                        const int arow = warp * 32 + mb * 16 + (lane & 7) + ((lane >> 3) & 1) * 8;
                        const uint32_t acol = (uint32_t)(kk * 2) + (uint32_t)(lane >> 4) * 16u;
                        ldsm_x4(afrag[mb], abase + sw128((uint32_t)(arow * 128) + acol));
                    }
#pragma unroll
                    for (int j = 0; j < 16; ++j) {
                        const int brow = 8 * j + (lane & 7);
                        const uint32_t bcol = (uint32_t)(kk * 2) + ((uint32_t)(lane >> 3) & 1u) * 16u;
                        uint32_t bfrag[2];
                        ldsm_x2(bfrag, bbase + sw128((uint32_t)(brow * 128) + bcol));
                        mma_bf16(acc[0][j], afrag[0], bfrag);
                        mma_bf16(acc[1][j], afrag[1], bfrag);
                    }
                }
            }

            // Epilogue: mask, online softmax, store raw scores
            const bool diag = (kt == qt);
#pragma unroll
            for (int mb = 0; mb < 2; mb++) {
#pragma unroll
                for (int rg = 0; rg < 2; rg++) {
                    const int row = warp * 32 + mb * 16 + rg * 8 + (lane >> 2);
                    float sv[32];
                    float mx = -1e30f;
#pragma unroll
                    for (int j = 0; j < 16; j++) {
                        const int c0 = 8 * j + (lane & 3) * 2;
                        float s0 = acc[mb][j][2 * rg] * SCALE;
                        float s1 = acc[mb][j][2 * rg + 1] * SCALE;
                        if (diag) {
                            if (c0 > row) s0 = -1e9f;
                            if (c0 + 1 > row) s1 = -1e9f;
                        }
                        sv[2 * j] = s0;
                        sv[2 * j + 1] = s1;
                        mx = fmaxf(mx, fmaxf(s0, s1));
                    }
                    mx = fmaxf(mx, __shfl_xor_sync(0xffffffffu, mx, 1));
                    mx = fmaxf(mx, __shfl_xor_sync(0xffffffffu, mx, 2));

                    const float mn = fmaxf(m[mb][rg], mx);
                    float ps = 0.0f;
#pragma unroll
                    for (int c = 0; c < 32; c++) ps += __expf(sv[c] - mn);
                    ps += __shfl_xor_sync(0xffffffffu, ps, 1);
                    ps += __shfl_xor_sync(0xffffffffu, ps, 2);

                    l[mb][rg] = l[mb][rg] * __expf(m[mb][rg] - mn) + ps;
                    m[mb][rg] = mn;

                    float* dst = SC + ((size_t)bh * S + r0 + row) * S + kt * 128;
#pragma unroll
                    for (int j = 0; j < 16; j++)
                        *((float2*)(dst + 8 * j + (lane & 3) * 2)) =
                            make_float2(sv[2 * j], sv[2 * j + 1]);
                }
            }
        }

        if ((lane & 3) == 0) {
#pragma unroll
            for (int mb = 0; mb < 2; mb++)
#pragma unroll
                for (int rg = 0; rg < 2; rg++) {
                    const int row = warp * 32 + mb * 16 + rg * 8 + (lane >> 2);
                    g_m[bh * S + r0 + row] = m[mb][rg];
                    g_l[bh * S + r0 + row] = l[mb][rg];
                }
        }
    }
}

// ---------------------------------------------------------------------------
// Pass 2 (unchanged best): probs -> gmem + smem; context = P @ V.
// ---------------------------------------------------------------------------
__global__ void __launch_bounds__(256, 2)
attn_pass2(const float* __restrict__ V, float* __restrict__ SC,
           float* __restrict__ CTX)
{
    extern __shared__ float smf[];
    float* sV = smf;               // 128 x PV
    float* sP = smf + 128 * PV;    // 128 x PP

    const int tid = threadIdx.x;
    const int tx = tid & 15;
    const int ty = tid >> 4;
    const int dgrp = tid & 7;
    const int rowgrp = tid >> 3;
    const int pid = blockIdx.x;
    const int bh = blockIdx.y;

    for (int half = 0; half < 2; ++half) {
        const int qt = half ? (15 - pid) : pid;
        const int r0 = qt * 128;

        float m[8], rl[8];
#pragma unroll
        for (int rr = 0; rr < 8; rr++) {
            const int gi = bh * S + r0 + ty * 8 + rr;
            m[rr] = g_m[gi];
            rl[rr] = 1.0f / g_l[gi];
        }

        unsigned long long acc[4][4];
#pragma unroll
        for (int rr = 0; rr < 4; rr++)
#pragma unroll
            for (int dp = 0; dp < 4; dp++) acc[rr][dp] = 0ull;

        for (int kt = 0; kt <= qt; ++kt) {
            __syncthreads();
            {
                const float* vbase = V + ((size_t)bh * S + kt * 128) * D;
                for (int i = tid; i < 128 * 16; i += 256) {
                    int row = i >> 4, c4 = i & 15;
                    float4 v = ((const float4*)(vbase + row * D))[c4];
                    *((float4*)(sV + row * PV + 4 * c4)) = v;
                }
            }

#pragma unroll 1
            for (int rr = 0; rr < 8; rr++) {
                const int row = ty * 8 + rr;
                float* srow = SC + ((size_t)bh * S + r0 + row) * S + kt * 128;
#pragma unroll
                for (int cc = 0; cc < 2; cc++) {
                    const int col = 4 * tx + 64 * cc;
                    float4 s4 = *((const float4*)(srow + col));
                    float4 p4;
                    p4.x = __expf(s4.x - m[rr]) * rl[rr];
                    p4.y = __expf(s4.y - m[rr]) * rl[rr];
                    p4.z = __expf(s4.z - m[rr]) * rl[rr];
                    p4.w = __expf(s4.w - m[rr]) * rl[rr];
                    *((float4*)(srow + col)) = p4;
                    *((float4*)(sP + row * PP + col)) = p4;
                }
            }
            __syncthreads();

#pragma unroll 1
            for (int c = 0; c < 128; c += 4) {
                float4 p4[4];
#pragma unroll
                for (int rr = 0; rr < 4; rr++)
                    p4[rr] = *((const float4*)(sP + (rowgrp * 4 + rr) * PP + c));
#pragma unroll
                for (int s = 0; s < 4; s++) {
                    const float* vrow = sV + (c + s) * PV + dgrp * 8;
                    unsigned long long vv[4];
                    {
                        ulonglong2 a = *((const ulonglong2*)(vrow));
                        ulonglong2 b = *((const ulonglong2*)(vrow + 4));
                        vv[0] = a.x; vv[1] = a.y; vv[2] = b.x; vv[3] = b.y;
                    }
#pragma unroll
                    for (int rr = 0; rr < 4; rr++) {
                        const float psc = (s == 0) ? p4[rr].x : (s == 1) ? p4[rr].y
                                        : (s == 2) ? p4[rr].z : p4[rr].w;
                        unsigned long long pd = dup2(psc);
#pragma unroll
                        for (int dp = 0; dp < 4; dp++) fma2(acc[rr][dp], pd, vv[dp]);
                    }
                }
            }
        }

#pragma unroll
        for (int rr = 0; rr < 4; rr++) {
            const int row = rowgrp * 4 + rr;
            float* crow = CTX + ((size_t)bh * S + r0 + row) * D + dgrp * 8;
            float2 a = unpack2(acc[rr][0]);
            float2 b = unpack2(acc[rr][1]);
            float2 c2 = unpack2(acc[rr][2]);
            float2 d2 = unpack2(acc[rr][3]);
            *((float4*)(crow))     = make_float4(a.x, a.y, b.x, b.y);
            *((float4*)(crow + 4)) = make_float4(c2.x, c2.y, d2.x, d2.y);
        }

#pragma unroll
        for (int rr = 0; rr < 4; rr++)
#pragma unroll
            for (int dp = 0; dp < 4; dp++) acc[rr][dp] = 0ull;
    }
}

// ---------------------------------------------------------------------------
extern "C" void kernel_launch(void* const* d_in, const int* in_sizes, int n_in,
                              void* d_out, int out_size)
{
    const float* q = (const float*)d_in[0];
    const float* k = (const float*)d_in[1];
    const float* v = (const float*)d_in[2];

    float* out = (float*)d_out;
    float* ctx = out;                 // [BH, S, D]
    float* sc  = out + CTX_ELEMS;     // [BH, S, S]

    const int smem2 = (128 * PV + 128 * PP) * sizeof(float);   // 102,400 B
    cudaFuncSetAttribute(attn_pass1, cudaFuncAttributeMaxDynamicSharedMemorySize, SM1_TOTAL);
    cudaFuncSetAttribute(attn_pass2, cudaFuncAttributeMaxDynamicSharedMemorySize, smem2);

    attn_pass1<<<dim3(8, BH), 128, SM1_TOTAL>>>(q, k, sc);
    attn_pass2<<<dim3(8, BH), 256, smem2>>>(v, sc, ctx);
}

// round 15
// speedup vs baseline: 1.6431x; 1.2507x over previous
#include <cuda_runtime.h>
#include <cuda_bf16.h>
#include <cstdint>

constexpr int S = 2048, D = 64;
constexpr int BH = 32;
constexpr float SCALE = 0.125f;
constexpr size_t CTX_ELEMS = (size_t)BH * S * D;

__device__ float g_m[BH * S];
__device__ float g_l[BH * S];

// ---- bf16 split helpers ----
__device__ __forceinline__ uint32_t bf2pack(float a, float b) {
    __nv_bfloat162 t = __floats2bfloat162_rn(a, b);
    return *reinterpret_cast<uint32_t*>(&t);
}
__device__ __forceinline__ float bfres(float a) {
    return a - __bfloat162float(__float2bfloat16(a));
}

// ---- smem addressing ----
__device__ __forceinline__ uint32_t smem_u32(const void* p) {
    uint32_t a;
    asm("{ .reg .u64 t; cvta.to.shared.u64 t, %1; cvt.u32.u64 %0, t; }" : "=r"(a) : "l"(p));
    return a;
}
__device__ __forceinline__ uint32_t sw128(uint32_t off) { return off ^ ((off >> 3) & 0x70); }

// ---- ldmatrix / mma wrappers (plain sm_80+ PTX) ----
__device__ __forceinline__ void ldsm_x4(uint32_t* r, uint32_t addr) {
    asm volatile("ldmatrix.sync.aligned.m8n8.x4.shared.b16 {%0,%1,%2,%3}, [%4];"
                 : "=r"(r[0]), "=r"(r[1]), "=r"(r[2]), "=r"(r[3]) : "r"(addr));
}
// non-trans: for operands stored [n][k] (k-contiguous) — pairs differ in k
__device__ __forceinline__ void ldsm_x2(uint32_t* r, uint32_t addr) {
    asm volatile("ldmatrix.sync.aligned.m8n8.x2.shared.b16 {%0,%1}, [%2];"
                 : "=r"(r[0]), "=r"(r[1]) : "r"(addr));
}
// trans: for operands stored [k][n] (n-contiguous) — pairs differ in k (row)
__device__ __forceinline__ void ldsm_x2t(uint32_t* r, uint32_t addr) {
    asm volatile("ldmatrix.sync.aligned.m8n8.x2.trans.shared.b16 {%0,%1}, [%2];"
                 : "=r"(r[0]), "=r"(r[1]) : "r"(addr));
}
__device__ __forceinline__ void mma_bf16(float* d, const uint32_t* a, const uint32_t* b) {
    asm volatile(
        "mma.sync.aligned.m16n8k16.row.col.f32.bf16.bf16.f32 "
        "{%0,%1,%2,%3}, {%4,%5,%6,%7}, {%8,%9}, {%0,%1,%2,%3};"
        : "+f"(d[0]), "+f"(d[1]), "+f"(d[2]), "+f"(d[3])
        : "r"(a[0]), "r"(a[1]), "r"(a[2]), "r"(a[3]), "r"(b[0]), "r"(b[1]));
}

// pass1 smem layout (bytes): 4 tiles of 128 rows x 64 bf16 (128B rows, SW128)
constexpr int TILE_B = 128 * 128;    // 16384
constexpr int SM_QHI = 0;
constexpr int SM_QLO = TILE_B;
constexpr int SM_KHI = 2 * TILE_B;
constexpr int SM_KLO = 3 * TILE_B;
constexpr int SM1_TOTAL = 4 * TILE_B;   // 65536 B

// pass2 smem layout: V hi/lo (128k x 64d bf16) + P hi/lo (2 sub-tiles of 128r x 64c)
constexpr int SM2_VHI = 0;
constexpr int SM2_VLO = TILE_B;
constexpr int SM2_PHI = 2 * TILE_B;   // + (sub)*TILE_B, sub in {0,1}
constexpr int SM2_PLO = 4 * TILE_B;   // + (sub)*TILE_B
constexpr int SM2_TOTAL = 6 * TILE_B; // 98304 B

// ---------------------------------------------------------------------------
// Pass 1 (HMMA, unchanged from passing R14): scores -> SC; m/l; zero-fill.
// ---------------------------------------------------------------------------
__global__ void __launch_bounds__(128, 2)
attn_pass1(const float* __restrict__ Q, const float* __restrict__ K,
           float* __restrict__ SC)
{
    extern __shared__ char smem[];
    const uint32_t sb = smem_u32(smem);

    const int tid = threadIdx.x;
    const int lane = tid & 31;
    const int warp = tid >> 5;
    const int pid = blockIdx.x;
    const int bh = blockIdx.y;

    {
        const float4 z = make_float4(0.f, 0.f, 0.f, 0.f);
#pragma unroll
        for (int half = 0; half < 2; ++half) {
            const int qt = half ? (15 - pid) : pid;
            const int c0 = (qt + 1) * 128;
            if (c0 < S) {
                const int w4 = (S - c0) >> 2;
                const int r0 = qt * 128;
                for (int i = tid; i < 128 * w4; i += 128) {
                    const int row = i / w4;
                    const int c4 = i - row * w4;
                    *((float4*)(SC + ((size_t)bh * S + r0 + row) * S + c0 + 4 * c4)) = z;
                }
            }
        }
    }

    for (int half = 0; half < 2; ++half) {
        const int qt = half ? (15 - pid) : pid;
        const int r0 = qt * 128;

        __syncthreads();
        {
            const float* qbase = Q + ((size_t)bh * S + r0) * D;
            for (int i = tid; i < 128 * 16; i += 128) {
                int row = i >> 4, c4 = i & 15;
                float4 v = ((const float4*)(qbase + row * D))[c4];
                uint32_t off = sw128((uint32_t)(row * 128 + c4 * 8));
                *((uint2*)(smem + SM_QHI + off)) =
                    make_uint2(bf2pack(v.x, v.y), bf2pack(v.z, v.w));
                *((uint2*)(smem + SM_QLO + off)) =
                    make_uint2(bf2pack(bfres(v.x), bfres(v.y)), bf2pack(bfres(v.z), bfres(v.w)));
            }
        }

        float m[2][2], l[2][2];
#pragma unroll
        for (int a = 0; a < 2; a++)
#pragma unroll
            for (int b = 0; b < 2; b++) { m[a][b] = -1e30f; l[a][b] = 0.0f; }

        for (int kt = 0; kt <= qt; ++kt) {
            __syncthreads();
            {
                const float* kbase = K + ((size_t)bh * S + kt * 128) * D;
                for (int i = tid; i < 128 * 16; i += 128) {
                    int row = i >> 4, c4 = i & 15;
                    float4 v = ((const float4*)(kbase + row * D))[c4];
                    uint32_t off = sw128((uint32_t)(row * 128 + c4 * 8));
                    *((uint2*)(smem + SM_KHI + off)) =
                        make_uint2(bf2pack(v.x, v.y), bf2pack(v.z, v.w));
                    *((uint2*)(smem + SM_KLO + off)) =
                        make_uint2(bf2pack(bfres(v.x), bfres(v.y)),
                                   bf2pack(bfres(v.z), bfres(v.w)));
                }
            }
            __syncthreads();

            float acc[2][16][4];
#pragma unroll
            for (int mb = 0; mb < 2; mb++)
#pragma unroll
                for (int j = 0; j < 16; j++)
#pragma unroll
                    for (int x = 0; x < 4; x++) acc[mb][j][x] = 0.0f;

#pragma unroll
            for (int p = 0; p < 3; ++p) {
                const uint32_t abase = sb + ((p == 2) ? SM_QLO : SM_QHI);
                const uint32_t bbase = sb + ((p == 1) ? SM_KLO : SM_KHI);
#pragma unroll
                for (int ks = 0; ks < 4; ++ks) {
                    const int kk = 16 * ks;
                    uint32_t afrag[2][4];
#pragma unroll
                    for (int mb = 0; mb < 2; mb++) {
                        const int arow = warp * 32 + mb * 16 + (lane & 7) + ((lane >> 3) & 1) * 8;
                        const uint32_t acol = (uint32_t)(kk * 2) + (uint32_t)(lane >> 4) * 16u;
                        ldsm_x4(afrag[mb], abase + sw128((uint32_t)(arow * 128) + acol));
                    }
#pragma unroll
                    for (int j = 0; j < 16; ++j) {
                        const int brow = 8 * j + (lane & 7);
                        const uint32_t bcol = (uint32_t)(kk * 2) + ((uint32_t)(lane >> 3) & 1u) * 16u;
                        uint32_t bfrag[2];
                        ldsm_x2(bfrag, bbase + sw128((uint32_t)(brow * 128) + bcol));
                        mma_bf16(acc[0][j], afrag[0], bfrag);
                        mma_bf16(acc[1][j], afrag[1], bfrag);
                    }
                }
            }

            const bool diag = (kt == qt);
#pragma unroll
            for (int mb = 0; mb < 2; mb++) {
#pragma unroll
                for (int rg = 0; rg < 2; rg++) {
                    const int row = warp * 32 + mb * 16 + rg * 8 + (lane >> 2);
                    float sv[32];
                    float mx = -1e30f;
#pragma unroll
                    for (int j = 0; j < 16; j++) {
                        const int c0 = 8 * j + (lane & 3) * 2;
                        float s0 = acc[mb][j][2 * rg] * SCALE;
                        float s1 = acc[mb][j][2 * rg + 1] * SCALE;
                        if (diag) {
                            if (c0 > row) s0 = -1e9f;
                            if (c0 + 1 > row) s1 = -1e9f;
                        }
                        sv[2 * j] = s0;
                        sv[2 * j + 1] = s1;
                        mx = fmaxf(mx, fmaxf(s0, s1));
                    }
                    mx = fmaxf(mx, __shfl_xor_sync(0xffffffffu, mx, 1));
                    mx = fmaxf(mx, __shfl_xor_sync(0xffffffffu, mx, 2));

                    const float mn = fmaxf(m[mb][rg], mx);
                    float ps = 0.0f;
#pragma unroll
                    for (int c = 0; c < 32; c++) ps += __expf(sv[c] - mn);
                    ps += __shfl_xor_sync(0xffffffffu, ps, 1);
                    ps += __shfl_xor_sync(0xffffffffu, ps, 2);

                    l[mb][rg] = l[mb][rg] * __expf(m[mb][rg] - mn) + ps;
                    m[mb][rg] = mn;

                    float* dst = SC + ((size_t)bh * S + r0 + row) * S + kt * 128;
#pragma unroll
                    for (int j = 0; j < 16; j++)
                        *((float2*)(dst + 8 * j + (lane & 3) * 2)) =
                            make_float2(sv[2 * j], sv[2 * j + 1]);
                }
            }
        }

        if ((lane & 3) == 0) {
#pragma unroll
            for (int mb = 0; mb < 2; mb++)
#pragma unroll
                for (int rg = 0; rg < 2; rg++) {
                    const int row = warp * 32 + mb * 16 + rg * 8 + (lane >> 2);
                    g_m[bh * S + r0 + row] = m[mb][rg];
                    g_l[bh * S + r0 + row] = l[mb][rg];
                }
        }
    }
}

// ---------------------------------------------------------------------------
// Pass 2 (HMMA PV): probs = exp(s-m)/l -> gmem + bf16 hi/lo smem; ctx via MMA.
// Grid (8,32) paired. 256 threads = 8 warps; warp w owns ctx rows w*16..+15.
// Prob phase: thread owns row tid>>1, col half (tid&1)*64.
// ---------------------------------------------------------------------------
__global__ void __launch_bounds__(256, 2)
attn_pass2(const float* __restrict__ V, float* __restrict__ SC,
           float* __restrict__ CTX)
{
    extern __shared__ char sm2[];
    const uint32_t sb = smem_u32(sm2);

    const int tid = threadIdx.x;
    const int lane = tid & 31;
    const int warp = tid >> 5;       // 0..7
    const int prow = tid >> 1;       // 0..127
    const int psub = tid & 1;        // col half / sub-tile
    const int pid = blockIdx.x;
    const int bh = blockIdx.y;

    for (int half = 0; half < 2; ++half) {
        const int qt = half ? (15 - pid) : pid;
        const int r0 = qt * 128;

        const float mrow = g_m[bh * S + r0 + prow];
        const float rlrow = 1.0f / g_l[bh * S + r0 + prow];

        float cacc[8][4];
#pragma unroll
        for (int j = 0; j < 8; j++)
#pragma unroll
            for (int x = 0; x < 4; x++) cacc[j][x] = 0.0f;

        for (int kt = 0; kt <= qt; ++kt) {
            __syncthreads();   // prior MMA done reading V/P tiles
            // Load V tile (128 k-rows x 64 d) -> bf16 hi/lo, SW128
            {
                const float* vbase = V + ((size_t)bh * S + kt * 128) * D;
                for (int i = tid; i < 128 * 16; i += 256) {
                    int row = i >> 4, c4 = i & 15;
                    float4 v = ((const float4*)(vbase + row * D))[c4];
                    uint32_t off = sw128((uint32_t)(row * 128 + c4 * 8));
                    *((uint2*)(sm2 + SM2_VHI + off)) =
                        make_uint2(bf2pack(v.x, v.y), bf2pack(v.z, v.w));
                    *((uint2*)(sm2 + SM2_VLO + off)) =
                        make_uint2(bf2pack(bfres(v.x), bfres(v.y)),
                                   bf2pack(bfres(v.z), bfres(v.w)));
                }
            }

            // Prob phase: read scores, exp, write fp32 probs + bf16 hi/lo smem
            {
                float* srow = SC + ((size_t)bh * S + r0 + prow) * S + kt * 128 + psub * 64;
                char* phidst = sm2 + SM2_PHI + psub * TILE_B;
                char* plodst = sm2 + SM2_PLO + psub * TILE_B;
#pragma unroll 4
                for (int c4 = 0; c4 < 16; ++c4) {
                    float4 s4 = ((const float4*)srow)[c4];
                    float4 p4;
                    p4.x = __expf(s4.x - mrow) * rlrow;
                    p4.y = __expf(s4.y - mrow) * rlrow;
                    p4.z = __expf(s4.z - mrow) * rlrow;
                    p4.w = __expf(s4.w - mrow) * rlrow;
                    ((float4*)srow)[c4] = p4;
                    uint32_t off = sw128((uint32_t)(prow * 128 + c4 * 8));
                    *((uint2*)(phidst + off)) =
                        make_uint2(bf2pack(p4.x, p4.y), bf2pack(p4.z, p4.w));
                    *((uint2*)(plodst + off)) =
                        make_uint2(bf2pack(bfres(p4.x), bfres(p4.y)),
                                   bf2pack(bfres(p4.z), bfres(p4.w)));
                }
            }
            __syncthreads();   // P/V tiles ready

            // PV MMA: ctx[m=row, n=d] += P[row,k] * V[k,d]
#pragma unroll 1
            for (int ks = 0; ks < 8; ++ks) {
                const int sub = ks >> 2;
                const uint32_t kkb = (uint32_t)((ks & 3) * 32);   // bytes within sub-tile row
                const int arow = warp * 16 + (lane & 7) + ((lane >> 3) & 1) * 8;
                const uint32_t aoff = sw128((uint32_t)(arow * 128) + kkb + (uint32_t)(lane >> 4) * 16u);
                uint32_t aPhi[4], aPlo[4];
                ldsm_x4(aPhi, sb + SM2_PHI + sub * TILE_B + aoff);
                ldsm_x4(aPlo, sb + SM2_PLO + sub * TILE_B + aoff);

                const int brow = ks * 16 + (lane & 7) + ((lane >> 3) & 1) * 8;
#pragma unroll
                for (int j = 0; j < 8; ++j) {
                    const uint32_t boff = sw128((uint32_t)(brow * 128) + (uint32_t)(j * 16));
                    uint32_t bhi[2], blo[2];
                    ldsm_x2t(bhi, sb + SM2_VHI + boff);
                    ldsm_x2t(blo, sb + SM2_VLO + boff);
                    mma_bf16(cacc[j], aPhi, bhi);
                    mma_bf16(cacc[j], aPlo, bhi);
                    mma_bf16(cacc[j], aPhi, blo);
                }
            }
        }

        // Write context from fragments: warp rows w*16..+15
#pragma unroll
        for (int rg = 0; rg < 2; rg++) {
            const int row = warp * 16 + rg * 8 + (lane >> 2);
            float* crow = CTX + ((size_t)bh * S + r0 + row) * D;
#pragma unroll
            for (int j = 0; j < 8; j++)
                *((float2*)(crow + 8 * j + (lane & 3) * 2)) =
                    make_float2(cacc[j][2 * rg], cacc[j][2 * rg + 1]);
        }
    }
}

// ---------------------------------------------------------------------------
extern "C" void kernel_launch(void* const* d_in, const int* in_sizes, int n_in,
                              void* d_out, int out_size)
{
    const float* q = (const float*)d_in[0];
    const float* k = (const float*)d_in[1];
    const float* v = (const float*)d_in[2];

    float* out = (float*)d_out;
    float* ctx = out;                 // [BH, S, D]
    float* sc  = out + CTX_ELEMS;     // [BH, S, S]

    cudaFuncSetAttribute(attn_pass1, cudaFuncAttributeMaxDynamicSharedMemorySize, SM1_TOTAL);
    cudaFuncSetAttribute(attn_pass2, cudaFuncAttributeMaxDynamicSharedMemorySize, SM2_TOTAL);

    attn_pass1<<<dim3(8, BH), 128, SM1_TOTAL>>>(q, k, sc);
    attn_pass2<<<dim3(8, BH), 256, SM2_TOTAL>>>(v, sc, ctx);
}